// round 3
// baseline (speedup 1.0000x reference)
#include <cuda_runtime.h>

// Apply_Mask v3 — warp-per-slice, smem-staged, sel-gated fast copy path.
// 32768 slices of 32x32 fp32. Half the slices (T==0) are a pure copy.
// For T!=0: pass A (LDG->STS->fmax), REDUX max, smem idx scan, REDUX min,
// smem scale pass -> STG. Low register footprint => high occupancy.

#define H 32
#define W 32
#define HW 1024
#define WPC 8  // warps (slices) per CTA

__global__ void __launch_bounds__(32 * WPC, 6)
apply_mask_v3(const float* __restrict__ x,
              const int* __restrict__ T,
              const int* __restrict__ drop_block_ptr,
              float* __restrict__ out)
{
    __shared__ float4 sbuf[WPC][256];  // 32 KB

    const int warp = threadIdx.x >> 5;
    const int lane = threadIdx.x & 31;
    const int slice = blockIdx.x * WPC + warp;
    const size_t base = (size_t)slice * HW;

    const float4* __restrict__ xin = reinterpret_cast<const float4*>(x + base);
    float4* __restrict__ o = reinterpret_cast<float4*>(out + base);

    // ---- fast path: T == 0 -> out = x (warp-uniform branch) ----
    if (T[slice] == 0) {
#pragma unroll
        for (int j = 0; j < 8; j += 2) {
            float4 a = xin[(j + 0) * 32 + lane];
            float4 b = xin[(j + 1) * 32 + lane];
            o[(j + 0) * 32 + lane] = a;
            o[(j + 1) * 32 + lane] = b;
        }
        return;
    }

    // ---- pass A: load, stash to smem, running fmax (one float4 live) ----
    float m;
    {
        float4 a = xin[lane];
        sbuf[warp][lane] = a;
        m = fmaxf(fmaxf(a.x, a.y), fmaxf(a.z, a.w));
    }
#pragma unroll
    for (int j = 1; j < 8; j++) {
        float4 a = xin[j * 32 + lane];
        sbuf[warp][j * 32 + lane] = a;
        m = fmaxf(m, fmaxf(fmaxf(a.x, a.y), fmaxf(a.z, a.w)));
    }

    // ---- warp max: one 32-bit REDUX on order-preserving key ----
    unsigned u = __float_as_uint(m);
    unsigned key = u ^ (unsigned)(((int)u >> 31) | 0x80000000);
    key = __reduce_max_sync(0xffffffffu, key);
    unsigned mu = key ^ (unsigned)((~((int)key >> 31)) | 0x80000000);
    const float maxf = __uint_as_float(mu);

    // ---- first-occurrence index: equality scan over own smem values ----
    unsigned idx = HW;
#pragma unroll
    for (int j = 0; j < 8; j++) {
        float4 a = sbuf[warp][j * 32 + lane];
        const unsigned e = (unsigned)(j * 128 + lane * 4);
        if (a.x == maxf) idx = min(idx, e + 0u);
        if (a.y == maxf) idx = min(idx, e + 1u);
        if (a.z == maxf) idx = min(idx, e + 2u);
        if (a.w == maxf) idx = min(idx, e + 3u);
    }
    idx = __reduce_min_sync(0xffffffffu, idx);

    // ---- box + lambda ----
    const int mh = (int)(idx >> 5);
    const int mw = (int)(idx & (W - 1));
    const int db = drop_block_ptr ? *drop_block_ptr : 5;
    const int half = db >> 1;

    const int h1 = max(mh - half, 0);
    const int h2 = min(mh + half, H - 1);
    const int w1 = max(mw - half, 0);
    const int w2 = min(mw + half, W - 1);

    const int area = (h2 - h1 + 1) * (w2 - w1 + 1);
    const float lam = (float)HW / (float)(HW - area);

    // lane's elements: e = j*128 + lane*4 + i -> row = j*4 + (lane>>3),
    // col = (lane&7)*4 + i.
    const int rbase = lane >> 3;
    const int cbase = (lane & 7) * 4;

    bool in_col[4];
#pragma unroll
    for (int i = 0; i < 4; i++)
        in_col[i] = (unsigned)(cbase + i - w1) <= (unsigned)(w2 - w1);

    float row_scale[8];  // applied when in_col true (0 inside box, lam outside)
#pragma unroll
    for (int j = 0; j < 8; j++) {
        const int r = j * 4 + rbase;
        const bool in_row = (unsigned)(r - h1) <= (unsigned)(h2 - h1);
        row_scale[j] = in_row ? 0.0f : lam;
    }

    // ---- scale pass: re-read smem, multiply, store ----
#pragma unroll
    for (int j = 0; j < 8; j++) {
        float4 a = sbuf[warp][j * 32 + lane];
        float4 w4;
        w4.x = a.x * (in_col[0] ? row_scale[j] : lam);
        w4.y = a.y * (in_col[1] ? row_scale[j] : lam);
        w4.z = a.z * (in_col[2] ? row_scale[j] : lam);
        w4.w = a.w * (in_col[3] ? row_scale[j] : lam);
        o[j * 32 + lane] = w4;
    }
}

extern "C" void kernel_launch(void* const* d_in, const int* in_sizes, int n_in,
                              void* d_out, int out_size)
{
    const float* x = (const float*)d_in[0];
    const int* T = (const int*)d_in[1];
    const int* db = (n_in >= 3) ? (const int*)d_in[2] : nullptr;
    float* out = (float*)d_out;

    const int n_slices = in_sizes[0] / HW;       // 32768
    const int n_ctas = n_slices / WPC;           // 4096

    apply_mask_v3<<<n_ctas, 32 * WPC>>>(x, T, db, out);
}

// round 4
// speedup vs baseline: 1.1884x; 1.1884x over previous
#include <cuda_runtime.h>

// Apply_Mask v4 — v2 register-resident structure (front-batched LDG.128, MLP=8)
// + T loaded in parallel with bulk loads, reduction skipped for T==0 warps
// (branch AFTER all loads issue), + streaming cache hints (read/write once).

#define H 32
#define W 32
#define HW 1024
#define WPC 8

__global__ void __launch_bounds__(32 * WPC, 4)
apply_mask_v4(const float* __restrict__ x,
              const int* __restrict__ T,
              const int* __restrict__ drop_block_ptr,
              float* __restrict__ out)
{
    const int warp = threadIdx.x >> 5;
    const int lane = threadIdx.x & 31;
    const int slice = blockIdx.x * WPC + warp;
    const size_t base = (size_t)slice * HW;

    const float4* __restrict__ xin = reinterpret_cast<const float4*>(x + base);
    float4* __restrict__ o = reinterpret_cast<float4*>(out + base);

    // T load issues first, overlapping the bulk loads below.
    const int t = __ldg(T + slice);

    // ---- front-batched bulk load: 8 x LDG.128, streaming ----
    float4 v[8];
#pragma unroll
    for (int j = 0; j < 8; j++)
        v[j] = __ldcs(xin + j * 32 + lane);

    if (t != 0) {
        // ---- local max, pairwise tree (short dependency chain) ----
        float m01 = fmaxf(fmaxf(fmaxf(v[0].x, v[0].y), fmaxf(v[0].z, v[0].w)),
                          fmaxf(fmaxf(v[1].x, v[1].y), fmaxf(v[1].z, v[1].w)));
        float m23 = fmaxf(fmaxf(fmaxf(v[2].x, v[2].y), fmaxf(v[2].z, v[2].w)),
                          fmaxf(fmaxf(v[3].x, v[3].y), fmaxf(v[3].z, v[3].w)));
        float m45 = fmaxf(fmaxf(fmaxf(v[4].x, v[4].y), fmaxf(v[4].z, v[4].w)),
                          fmaxf(fmaxf(v[5].x, v[5].y), fmaxf(v[5].z, v[5].w)));
        float m67 = fmaxf(fmaxf(fmaxf(v[6].x, v[6].y), fmaxf(v[6].z, v[6].w)),
                          fmaxf(fmaxf(v[7].x, v[7].y), fmaxf(v[7].z, v[7].w)));
        float m = fmaxf(fmaxf(m01, m23), fmaxf(m45, m67));

        // ---- warp max: one 32-bit REDUX on order-preserving key ----
        unsigned u = __float_as_uint(m);
        unsigned key = u ^ (unsigned)(((int)u >> 31) | 0x80000000);
        key = __reduce_max_sync(0xffffffffu, key);
        unsigned mu = key ^ (unsigned)((~((int)key >> 31)) | 0x80000000);
        const float maxf = __uint_as_float(mu);

        // ---- first-occurrence index ----
        unsigned idx = HW;
        {
            const float* vf = &v[0].x;
#pragma unroll
            for (int j = 0; j < 8; j++) {
#pragma unroll
                for (int i = 0; i < 4; i++) {
                    const unsigned e = (unsigned)(j * 128 + lane * 4 + i);
                    if (vf[j * 4 + i] == maxf) idx = min(idx, e);
                }
            }
        }
        idx = __reduce_min_sync(0xffffffffu, idx);

        // ---- box + lambda ----
        const int mh = (int)(idx >> 5);
        const int mw = (int)(idx & (W - 1));
        const int db = drop_block_ptr ? *drop_block_ptr : 5;
        const int half = db >> 1;

        const int h1 = max(mh - half, 0);
        const int h2 = min(mh + half, H - 1);
        const int w1 = max(mw - half, 0);
        const int w2 = min(mw + half, W - 1);

        const int area = (h2 - h1 + 1) * (w2 - w1 + 1);
        const float lam = (float)HW / (float)(HW - area);

        // lane's elements: e = j*128 + lane*4 + i -> row = j*4 + (lane>>3),
        // col = (lane&7)*4 + i
        const int rbase = lane >> 3;
        const int cbase = (lane & 7) * 4;

        bool in_col[4];
#pragma unroll
        for (int i = 0; i < 4; i++)
            in_col[i] = (unsigned)(cbase + i - w1) <= (unsigned)(w2 - w1);

        float row_scale[8];
#pragma unroll
        for (int j = 0; j < 8; j++) {
            const int r = j * 4 + rbase;
            const bool in_row = (unsigned)(r - h1) <= (unsigned)(h2 - h1);
            row_scale[j] = in_row ? 0.0f : lam;
        }

#pragma unroll
        for (int j = 0; j < 8; j++) {
            float4 w4;
            w4.x = v[j].x * (in_col[0] ? row_scale[j] : lam);
            w4.y = v[j].y * (in_col[1] ? row_scale[j] : lam);
            w4.z = v[j].z * (in_col[2] ? row_scale[j] : lam);
            w4.w = v[j].w * (in_col[3] ? row_scale[j] : lam);
            __stcs(o + j * 32 + lane, w4);
        }
    } else {
        // ---- copy path: stores depend only on loads ----
#pragma unroll
        for (int j = 0; j < 8; j++)
            __stcs(o + j * 32 + lane, v[j]);
    }
}

extern "C" void kernel_launch(void* const* d_in, const int* in_sizes, int n_in,
                              void* d_out, int out_size)
{
    const float* x = (const float*)d_in[0];
    const int* T = (const int*)d_in[1];
    const int* db = (n_in >= 3) ? (const int*)d_in[2] : nullptr;
    float* out = (float*)d_out;

    const int n_slices = in_sizes[0] / HW;   // 32768
    const int n_ctas = n_slices / WPC;       // 4096

    apply_mask_v4<<<n_ctas, 32 * WPC>>>(x, T, db, out);
}